// round 1
// baseline (speedup 1.0000x reference)
#include <cuda_runtime.h>
#include <cuda_bf16.h>

#define TT   2048   // tokens
#define HH   2048   // hidden
#define II   1024   // intermediate
#define EE   16     // experts
#define TOPK 4

#define BM 128
#define BN 64
#define BK 16

// ---------------- scratch (device globals; no allocation allowed) ----------------
__device__ int   g_counts[EE];
__device__ int   g_tok[EE * TT];             // token id per expert slot
__device__ int   g_tslot[TT * TOPK];         // flat slot (e*TT + slot) per (token,k)
__device__ float g_twt[TT * TOPK];           // renormalized combine weight per (token,k)
__device__ float g_act[(size_t)EE * TT * II];   // 128 MB swiglu activations per slot
__device__ float g_h2 [(size_t)EE * TT * HH];   // 256 MB down-proj result per slot

// ---------------- kernels ----------------
__global__ void zero_counts_kernel() {
    if (threadIdx.x < EE) g_counts[threadIdx.x] = 0;
}

__global__ void router_kernel(const float* __restrict__ hs,
                              const float* __restrict__ gw) {
    const int t = blockIdx.x;
    __shared__ float xs[HH];
    __shared__ float logits[EE];

    const float* x = hs + (size_t)t * HH;
    for (int i = threadIdx.x; i < HH; i += blockDim.x) xs[i] = x[i];
    __syncthreads();

    const int warp = threadIdx.x >> 5;
    const int lane = threadIdx.x & 31;
    for (int e = warp; e < EE; e += 8) {
        const float* g = gw + (size_t)e * HH;
        float s = 0.f;
        for (int k = lane; k < HH; k += 32) s += xs[k] * g[k];
        #pragma unroll
        for (int o = 16; o; o >>= 1) s += __shfl_xor_sync(0xffffffffu, s, o);
        if (lane == 0) logits[e] = s;
    }
    __syncthreads();

    if (threadIdx.x == 0) {
        float lv[EE];
        #pragma unroll
        for (int e = 0; e < EE; e++) lv[e] = logits[e];
        int idx[TOPK]; float val[TOPK];
        #pragma unroll
        for (int k = 0; k < TOPK; k++) {
            float best = -1e30f; int bi = 0;
            for (int e = 0; e < EE; e++)
                if (lv[e] > best) { best = lv[e]; bi = e; }
            idx[k] = bi; val[k] = best; lv[bi] = -1e30f;
        }
        // renormalized top-k softmax == softmax over the top-k logits
        const float m = val[0];
        float w[TOPK], se = 0.f;
        #pragma unroll
        for (int k = 0; k < TOPK; k++) { w[k] = __expf(val[k] - m); se += w[k]; }
        const float inv = 1.f / se;
        #pragma unroll
        for (int k = 0; k < TOPK; k++) {
            const int e = idx[k];
            const int slot = atomicAdd(&g_counts[e], 1);
            g_tok[e * TT + slot]   = t;
            g_tslot[t * TOPK + k]  = e * TT + slot;
            g_twt[t * TOPK + k]    = w[k] * inv;
        }
    }
}

// h1 = X W1, h3 = X W3, act = silu(h1)*h3  (grouped, gathered rows)
__global__ __launch_bounds__(256, 2)
void gemm13_kernel(const float* __restrict__ hs,
                   const float* __restrict__ w1,
                   const float* __restrict__ w3) {
    const int e   = blockIdx.z;
    const int cnt = g_counts[e];
    const int m0  = blockIdx.y * BM;
    if (m0 >= cnt) return;
    const int n0  = blockIdx.x * BN;

    const float* W1 = w1 + (size_t)e * HH * II;
    const float* W3 = w3 + (size_t)e * HH * II;

    __shared__ float As [BK][BM];
    __shared__ float B1s[BK][BN];
    __shared__ float B3s[BK][BN];
    __shared__ int   rowTok[BM];

    const int tid = threadIdx.x;
    if (tid < BM) {
        const int m = m0 + tid;
        rowTok[tid] = (m < cnt) ? g_tok[e * TT + m] : -1;
    }
    __syncthreads();

    float acc1[8][4], acc3[8][4];
    #pragma unroll
    for (int i = 0; i < 8; i++)
        #pragma unroll
        for (int j = 0; j < 4; j++) { acc1[i][j] = 0.f; acc3[i][j] = 0.f; }

    const int tx = tid & 15;
    const int ty = tid >> 4;

    for (int k0 = 0; k0 < HH; k0 += BK) {
        // A tile: 128 rows x 16 k  = 512 float4 -> 2 per thread (gathered)
        #pragma unroll
        for (int it = 0; it < 2; it++) {
            const int i  = tid + it * 256;
            const int m  = i >> 2;      // 4 float4 per row
            const int kq = i & 3;
            const int tok = rowTok[m];
            float4 v = make_float4(0.f, 0.f, 0.f, 0.f);
            if (tok >= 0)
                v = *(const float4*)(hs + (size_t)tok * HH + k0 + kq * 4);
            As[kq * 4 + 0][m] = v.x;
            As[kq * 4 + 1][m] = v.y;
            As[kq * 4 + 2][m] = v.z;
            As[kq * 4 + 3][m] = v.w;
        }
        // B tiles: 16 k x 64 n = 256 float4 each -> 1 per thread
        {
            const int kk = tid >> 4;
            const int nq = tid & 15;
            const size_t boff = (size_t)(k0 + kk) * II + n0 + nq * 4;
            *(float4*)&B1s[kk][nq * 4] = *(const float4*)(W1 + boff);
            *(float4*)&B3s[kk][nq * 4] = *(const float4*)(W3 + boff);
        }
        __syncthreads();
        #pragma unroll
        for (int k = 0; k < BK; k++) {
            float a[8];
            *(float4*)&a[0] = *(const float4*)&As[k][ty * 8];
            *(float4*)&a[4] = *(const float4*)&As[k][ty * 8 + 4];
            const float4 b1v = *(const float4*)&B1s[k][tx * 4];
            const float4 b3v = *(const float4*)&B3s[k][tx * 4];
            const float bb1[4] = {b1v.x, b1v.y, b1v.z, b1v.w};
            const float bb3[4] = {b3v.x, b3v.y, b3v.z, b3v.w};
            #pragma unroll
            for (int i = 0; i < 8; i++)
                #pragma unroll
                for (int j = 0; j < 4; j++) {
                    acc1[i][j] += a[i] * bb1[j];
                    acc3[i][j] += a[i] * bb3[j];
                }
        }
        __syncthreads();
    }

    #pragma unroll
    for (int i = 0; i < 8; i++) {
        const int m = m0 + ty * 8 + i;
        if (m >= cnt) continue;
        float4 o;
        float* p = (float*)&o;
        #pragma unroll
        for (int j = 0; j < 4; j++) {
            const float x = acc1[i][j];
            const float s = x / (1.f + __expf(-x));   // silu
            p[j] = s * acc3[i][j];
        }
        *(float4*)(g_act + ((size_t)e * TT + m) * II + n0 + tx * 4) = o;
    }
}

// h2 = act W2  (grouped, rows are slots; no gather)
__global__ __launch_bounds__(256, 2)
void gemm2_kernel(const float* __restrict__ w2) {
    const int e   = blockIdx.z;
    const int cnt = g_counts[e];
    const int m0  = blockIdx.y * BM;
    if (m0 >= cnt) return;
    const int n0  = blockIdx.x * BN;

    const float* W2 = w2 + (size_t)e * II * HH;
    const float* A  = g_act + (size_t)e * TT * II;

    __shared__ float As[BK][BM];
    __shared__ float Bs[BK][BN];

    const int tid = threadIdx.x;
    float acc[8][4];
    #pragma unroll
    for (int i = 0; i < 8; i++)
        #pragma unroll
        for (int j = 0; j < 4; j++) acc[i][j] = 0.f;

    const int tx = tid & 15;
    const int ty = tid >> 4;

    for (int k0 = 0; k0 < II; k0 += BK) {
        #pragma unroll
        for (int it = 0; it < 2; it++) {
            const int i  = tid + it * 256;
            const int m  = i >> 2;
            const int kq = i & 3;
            float4 v = make_float4(0.f, 0.f, 0.f, 0.f);
            if (m0 + m < cnt)
                v = *(const float4*)(A + (size_t)(m0 + m) * II + k0 + kq * 4);
            As[kq * 4 + 0][m] = v.x;
            As[kq * 4 + 1][m] = v.y;
            As[kq * 4 + 2][m] = v.z;
            As[kq * 4 + 3][m] = v.w;
        }
        {
            const int kk = tid >> 4;
            const int nq = tid & 15;
            *(float4*)&Bs[kk][nq * 4] =
                *(const float4*)(W2 + (size_t)(k0 + kk) * HH + n0 + nq * 4);
        }
        __syncthreads();
        #pragma unroll
        for (int k = 0; k < BK; k++) {
            float a[8];
            *(float4*)&a[0] = *(const float4*)&As[k][ty * 8];
            *(float4*)&a[4] = *(const float4*)&As[k][ty * 8 + 4];
            const float4 bv = *(const float4*)&Bs[k][tx * 4];
            const float bb[4] = {bv.x, bv.y, bv.z, bv.w};
            #pragma unroll
            for (int i = 0; i < 8; i++)
                #pragma unroll
                for (int j = 0; j < 4; j++)
                    acc[i][j] += a[i] * bb[j];
        }
        __syncthreads();
    }

    #pragma unroll
    for (int i = 0; i < 8; i++) {
        const int m = m0 + ty * 8 + i;
        if (m >= cnt) continue;
        float4 o = make_float4(acc[i][0], acc[i][1], acc[i][2], acc[i][3]);
        *(float4*)(g_h2 + ((size_t)e * TT + m) * HH + n0 + tx * 4) = o;
    }
}

// out[t] = sum_k w_k * h2[slot(t,k)]   (fixed order -> deterministic)
__global__ void combine_kernel(float* __restrict__ out) {
    const int t = blockIdx.y;
    const int h = blockIdx.x * blockDim.x + threadIdx.x;
    float s = 0.f;
    #pragma unroll
    for (int k = 0; k < TOPK; k++) {
        const int   fs = g_tslot[t * TOPK + k];
        const float w  = g_twt [t * TOPK + k];
        s += w * g_h2[(size_t)fs * HH + h];
    }
    out[(size_t)t * HH + h] = s;
}

// ---------------- launch ----------------
extern "C" void kernel_launch(void* const* d_in, const int* in_sizes, int n_in,
                              void* d_out, int out_size) {
    const float* hs = (const float*)d_in[0];
    const float* gw = (const float*)d_in[1];
    const float* w1 = (const float*)d_in[2];
    const float* w3 = (const float*)d_in[3];
    const float* w2 = (const float*)d_in[4];
    float* out = (float*)d_out;

    zero_counts_kernel<<<1, 32>>>();
    router_kernel<<<TT, 256>>>(hs, gw);
    gemm13_kernel<<<dim3(II / BN, TT / BM, EE), 256>>>(hs, w1, w3);
    gemm2_kernel<<<dim3(HH / BN, TT / BM, EE), 256>>>(w2);
    combine_kernel<<<dim3(HH / 256, TT), 256>>>(out);
}

// round 3
// speedup vs baseline: 2.1641x; 2.1641x over previous
#include <cuda_runtime.h>
#include <cuda_bf16.h>
#include <cstdint>

#define TT   2048
#define HH   2048
#define II   1024
#define EE   16
#define TOPK 4

// ---------------- PTX helpers (sm_80-level only; target is plain sm_103) -------
__device__ __forceinline__ uint32_t smem_to_u32(const void* p) {
    uint32_t a;
    asm("{ .reg .u64 t; cvta.to.shared.u64 t, %1; cvt.u32.u64 %0, t; }"
        : "=r"(a) : "l"(p));
    return a;
}
__device__ __forceinline__ uint32_t lds32(uint32_t a) {
    uint32_t v;
    asm volatile("ld.shared.b32 %0, [%1];" : "=r"(v) : "r"(a));
    return v;
}
#define CP_ASYNC16(dst, src) \
    asm volatile("cp.async.cg.shared.global [%0], [%1], 16;" :: "r"(dst), "l"(src) : "memory")
#define CP_ASYNC16Z(dst, src, ssz) \
    asm volatile("cp.async.cg.shared.global [%0], [%1], 16, %2;" :: "r"(dst), "l"(src), "r"(ssz) : "memory")
#define CP_COMMIT()  asm volatile("cp.async.commit_group;" ::: "memory")
#define CP_WAIT(n)   asm volatile("cp.async.wait_group %0;" :: "n"(n) : "memory")

// D += A*B  (m16n8k16, bf16 in, f32 accum)
__device__ __forceinline__ void mma16816(float* c, const uint32_t* a, const uint32_t* b) {
    asm volatile(
        "mma.sync.aligned.m16n8k16.row.col.f32.bf16.bf16.f32 "
        "{%0,%1,%2,%3}, {%4,%5,%6,%7}, {%8,%9}, {%0,%1,%2,%3};"
        : "+f"(c[0]), "+f"(c[1]), "+f"(c[2]), "+f"(c[3])
        : "r"(a[0]), "r"(a[1]), "r"(a[2]), "r"(a[3]), "r"(b[0]), "r"(b[1]));
}

// ---------------- scratch ----------------
__device__ int   g_counts[EE];
__device__ int   g_tok[EE * TT];
__device__ int   g_tslot[TT * TOPK];
__device__ float g_twt[TT * TOPK];
__device__ float g_h2[(size_t)EE * TT * HH];
__device__ __nv_bfloat16 g_hshi[(size_t)TT * HH];
__device__ __nv_bfloat16 g_hslo[(size_t)TT * HH];
__device__ __nv_bfloat16 g_acthi[(size_t)EE * TT * II];
__device__ __nv_bfloat16 g_actlo[(size_t)EE * TT * II];
__device__ __nv_bfloat16 g_w13hi[(size_t)EE * 2 * II * HH];  // [e*2+mat][i][h]
__device__ __nv_bfloat16 g_w13lo[(size_t)EE * 2 * II * HH];
__device__ __nv_bfloat16 g_w2hi [(size_t)EE * HH * II];      // [e][h][i]
__device__ __nv_bfloat16 g_w2lo [(size_t)EE * HH * II];

__device__ __forceinline__ void split_bf16(float x, __nv_bfloat16& hi, __nv_bfloat16& lo) {
    hi = __float2bfloat16(x);
    lo = __float2bfloat16(x - __bfloat162float(hi));
}
__device__ __forceinline__ uint32_t pack2(__nv_bfloat16 a, __nv_bfloat16 b) {
    return (uint32_t)__bfloat16_as_ushort(a) | ((uint32_t)__bfloat16_as_ushort(b) << 16);
}

// ---------------- router ----------------
__global__ void zero_counts_kernel() {
    if (threadIdx.x < EE) g_counts[threadIdx.x] = 0;
}

__global__ void router_kernel(const float* __restrict__ hs,
                              const float* __restrict__ gw) {
    const int t = blockIdx.x;
    __shared__ float xs[HH];
    __shared__ float logits[EE];
    const float* x = hs + (size_t)t * HH;
    for (int i = threadIdx.x; i < HH; i += blockDim.x) xs[i] = x[i];
    __syncthreads();
    const int warp = threadIdx.x >> 5, lane = threadIdx.x & 31;
    for (int e = warp; e < EE; e += 8) {
        const float* g = gw + (size_t)e * HH;
        float s = 0.f;
        for (int k = lane; k < HH; k += 32) s += xs[k] * g[k];
        #pragma unroll
        for (int o = 16; o; o >>= 1) s += __shfl_xor_sync(0xffffffffu, s, o);
        if (lane == 0) logits[e] = s;
    }
    __syncthreads();
    if (threadIdx.x == 0) {
        float lv[EE];
        #pragma unroll
        for (int e = 0; e < EE; e++) lv[e] = logits[e];
        int idx[TOPK]; float val[TOPK];
        #pragma unroll
        for (int k = 0; k < TOPK; k++) {
            float best = -1e30f; int bi = 0;
            for (int e = 0; e < EE; e++) if (lv[e] > best) { best = lv[e]; bi = e; }
            idx[k] = bi; val[k] = best; lv[bi] = -1e30f;
        }
        const float m = val[0];
        float w[TOPK], se = 0.f;
        #pragma unroll
        for (int k = 0; k < TOPK; k++) { w[k] = __expf(val[k] - m); se += w[k]; }
        const float inv = 1.f / se;
        #pragma unroll
        for (int k = 0; k < TOPK; k++) {
            const int e = idx[k];
            const int slot = atomicAdd(&g_counts[e], 1);
            g_tok[e * TT + slot]  = t;
            g_tslot[t * TOPK + k] = e * TT + slot;
            g_twt[t * TOPK + k]   = w[k] * inv;
        }
    }
}

// ---------------- prepass: split hs ----------------
__global__ void prep_hs_kernel(const float* __restrict__ hs) {
    const size_t i = ((size_t)blockIdx.x * 256 + threadIdx.x) * 4;
    const float4 v = *(const float4*)(hs + i);
    __nv_bfloat16 h0, l0, h1, l1, h2, l2, h3, l3;
    split_bf16(v.x, h0, l0); split_bf16(v.y, h1, l1);
    split_bf16(v.z, h2, l2); split_bf16(v.w, h3, l3);
    *(uint2*)(g_hshi + i) = make_uint2(pack2(h0, h1), pack2(h2, h3));
    *(uint2*)(g_hslo + i) = make_uint2(pack2(l0, l1), pack2(l2, l3));
}

// ---------------- prepass: transpose + split weights ----------------
__global__ void prep_w13_kernel(const float* __restrict__ w1,
                                const float* __restrict__ w3) {
    __shared__ float s[32][33];
    const int z = blockIdx.z;            // e*2+mat
    const int e = z >> 1, mat = z & 1;
    const float* src = (mat ? w3 : w1) + (size_t)e * HH * II;
    const int i0 = blockIdx.x * 32, h0 = blockIdx.y * 32;
    const int tx = threadIdx.x, ty = threadIdx.y;
    #pragma unroll
    for (int j = 0; j < 4; j++)
        s[ty + 8 * j][tx] = src[(size_t)(h0 + ty + 8 * j) * II + i0 + tx];
    __syncthreads();
    #pragma unroll
    for (int j = 0; j < 4; j++) {
        const float x = s[tx][ty + 8 * j];
        __nv_bfloat16 hi, lo; split_bf16(x, hi, lo);
        const size_t o = ((size_t)z * II + i0 + ty + 8 * j) * HH + h0 + tx;
        g_w13hi[o] = hi; g_w13lo[o] = lo;
    }
}

__global__ void prep_w2_kernel(const float* __restrict__ w2) {
    __shared__ float s[32][33];
    const int e = blockIdx.z;
    const float* src = w2 + (size_t)e * II * HH;
    const int i0 = blockIdx.x * 32, h0 = blockIdx.y * 32;
    const int tx = threadIdx.x, ty = threadIdx.y;
    #pragma unroll
    for (int j = 0; j < 4; j++)
        s[ty + 8 * j][tx] = src[(size_t)(i0 + ty + 8 * j) * HH + h0 + tx];
    __syncthreads();
    #pragma unroll
    for (int j = 0; j < 4; j++) {
        const float x = s[tx][ty + 8 * j];
        __nv_bfloat16 hi, lo; split_bf16(x, hi, lo);
        const size_t o = ((size_t)e * HH + h0 + ty + 8 * j) * II + i0 + tx;
        g_w2hi[o] = hi; g_w2lo[o] = lo;
    }
}

// ---------------- gemm13: warp-MMA, split bf16, 3-term ----------------
// tile: 128 (m) x 64 (n) for BOTH h1 and h3; BK=32, double-buffered cp.async
#define STRIDE_H 40                        // halves per smem row (80B, 16B-mult, conflict-free)
#define G13_AB   (128 * STRIDE_H * 2)      // 10240 per A plane
#define G13_BB   (64 * STRIDE_H * 2)       // 5120 per B plane
#define G13_BUF  (2 * G13_AB + 4 * G13_BB) // 40960 per buffer
#define G13_SMEM (2 * G13_BUF + 1024)

__global__ __launch_bounds__(256)
void gemm13_wm(const __nv_bfloat16* __restrict__ dummy) {
    extern __shared__ char smem[];
    const int e    = blockIdx.z;
    const int cnt  = g_counts[e];
    const int m0b  = blockIdx.y * 128;
    if (m0b >= cnt) return;
    const int n0b  = blockIdx.x * 64;

    const int tid  = threadIdx.x;
    const int wid  = tid >> 5, lane = tid & 31;
    const int m0w  = (wid & 3) * 32;
    const int n0w  = (wid >> 2) * 32;
    const uint32_t sb = smem_to_u32(smem);

    int* rowTokS = (int*)(smem + 2 * G13_BUF);
    if (tid < 128) rowTokS[tid] = (m0b + tid < cnt) ? g_tok[e * TT + m0b + tid] : -1;
    __syncthreads();

    const __nv_bfloat16* srcB[4] = {
        g_w13hi + ((size_t)(e * 2 + 0) * II + n0b) * HH,
        g_w13lo + ((size_t)(e * 2 + 0) * II + n0b) * HH,
        g_w13hi + ((size_t)(e * 2 + 1) * II + n0b) * HH,
        g_w13lo + ((size_t)(e * 2 + 1) * II + n0b) * HH };

    float acc1[2][4][4], acc3[2][4][4];
    #pragma unroll
    for (int mt = 0; mt < 2; mt++)
        #pragma unroll
        for (int nt = 0; nt < 4; nt++)
            #pragma unroll
            for (int j = 0; j < 4; j++) { acc1[mt][nt][j] = 0.f; acc3[mt][nt][j] = 0.f; }

    auto load_chunk = [&](int buf, int c) {
        const int k0 = c * 32;
        const uint32_t base = sb + buf * G13_BUF;
        // A planes: 128 rows x 32k, gathered, zero-fill pads
        #pragma unroll
        for (int pl = 0; pl < 2; pl++) {
            const __nv_bfloat16* sp = pl ? g_hslo : g_hshi;
            #pragma unroll
            for (int it = 0; it < 2; it++) {
                const int idx = tid + it * 256;
                const int row = idx >> 2, seg = idx & 3;
                const int tok = rowTokS[row];
                const uint32_t dst = base + pl * G13_AB + row * 80 + seg * 16;
                const __nv_bfloat16* s =
                    (tok >= 0 ? sp + (size_t)tok * HH : sp) + k0 + seg * 8;
                const uint32_t ssz = (tok >= 0) ? 16u : 0u;
                CP_ASYNC16Z(dst, s, ssz);
            }
        }
        // B planes: 4 x (64 rows x 32k)
        #pragma unroll
        for (int pl = 0; pl < 4; pl++) {
            const int row = tid >> 2, seg = tid & 3;
            const uint32_t dst = base + 2 * G13_AB + pl * G13_BB + row * 80 + seg * 16;
            CP_ASYNC16(dst, srcB[pl] + (size_t)row * HH + k0 + seg * 8);
        }
        CP_COMMIT();
    };

    const int NC = HH / 32;   // 64
    load_chunk(0, 0);
    load_chunk(1, 1);

    for (int c = 0; c < NC; c++) {
        if (c == NC - 1) { CP_WAIT(0); } else { CP_WAIT(1); }
        __syncthreads();
        const int buf = c & 1;
        const uint32_t aH = sb + buf * G13_BUF;
        const uint32_t aL = aH + G13_AB;
        const uint32_t bB = aH + 2 * G13_AB;
        #pragma unroll
        for (int kk = 0; kk < 2; kk++) {
            const uint32_t koff = (kk * 16 + 2 * (lane & 3)) * 2;
            uint32_t ah[2][4], al[2][4];
            #pragma unroll
            for (int mt = 0; mt < 2; mt++) {
                const uint32_t ro = (m0w + mt * 16 + (lane >> 2)) * 80 + koff;
                ah[mt][0] = lds32(aH + ro);            ah[mt][1] = lds32(aH + ro + 640);
                ah[mt][2] = lds32(aH + ro + 16);       ah[mt][3] = lds32(aH + ro + 656);
                al[mt][0] = lds32(aL + ro);            al[mt][1] = lds32(aL + ro + 640);
                al[mt][2] = lds32(aL + ro + 16);       al[mt][3] = lds32(aL + ro + 656);
            }
            uint32_t b1h[4][2], b1l[4][2], b3h[4][2], b3l[4][2];
            #pragma unroll
            for (int nt = 0; nt < 4; nt++) {
                const uint32_t ro = (n0w + nt * 8 + (lane >> 2)) * 80 + koff;
                b1h[nt][0] = lds32(bB + ro);                 b1h[nt][1] = lds32(bB + ro + 16);
                b1l[nt][0] = lds32(bB + G13_BB + ro);        b1l[nt][1] = lds32(bB + G13_BB + ro + 16);
                b3h[nt][0] = lds32(bB + 2 * G13_BB + ro);    b3h[nt][1] = lds32(bB + 2 * G13_BB + ro + 16);
                b3l[nt][0] = lds32(bB + 3 * G13_BB + ro);    b3l[nt][1] = lds32(bB + 3 * G13_BB + ro + 16);
            }
            #pragma unroll
            for (int mt = 0; mt < 2; mt++)
                #pragma unroll
                for (int nt = 0; nt < 4; nt++) {
                    mma16816(acc1[mt][nt], ah[mt], b1h[nt]);
                    mma16816(acc1[mt][nt], al[mt], b1h[nt]);
                    mma16816(acc1[mt][nt], ah[mt], b1l[nt]);
                    mma16816(acc3[mt][nt], ah[mt], b3h[nt]);
                    mma16816(acc3[mt][nt], al[mt], b3h[nt]);
                    mma16816(acc3[mt][nt], ah[mt], b3l[nt]);
                }
        }
        __syncthreads();
        if (c + 2 < NC) load_chunk(buf, c + 2);
    }

    // epilogue: silu(h1)*h3 -> split bf16 -> smem stage -> coalesced store
    CP_WAIT(0);
    __syncthreads();
    char* stHi = smem;                     // 128 x 72 halves
    char* stLo = smem + 128 * 72 * 2;
    #pragma unroll
    for (int mt = 0; mt < 2; mt++)
        #pragma unroll
        for (int nt = 0; nt < 4; nt++) {
            const int gr = m0w + mt * 16 + (lane >> 2);
            const int cb = n0w + nt * 8 + 2 * (lane & 3);
            float a[4];
            #pragma unroll
            for (int j = 0; j < 4; j++) {
                const float x = acc1[mt][nt][j];
                a[j] = (x / (1.f + __expf(-x))) * acc3[mt][nt][j];
            }
            __nv_bfloat16 h0, l0, h1, l1, h2, l2, h3, l3;
            split_bf16(a[0], h0, l0); split_bf16(a[1], h1, l1);
            split_bf16(a[2], h2, l2); split_bf16(a[3], h3, l3);
            *(uint32_t*)(stHi + (gr * 72 + cb) * 2)       = pack2(h0, h1);
            *(uint32_t*)(stHi + ((gr + 8) * 72 + cb) * 2) = pack2(h2, h3);
            *(uint32_t*)(stLo + (gr * 72 + cb) * 2)       = pack2(l0, l1);
            *(uint32_t*)(stLo + ((gr + 8) * 72 + cb) * 2) = pack2(l2, l3);
        }
    __syncthreads();
    #pragma unroll
    for (int it = 0; it < 4; it++) {
        const int idx = tid + it * 256;           // 0..1023
        const int row = idx >> 3, seg = idx & 7;
        if (m0b + row < cnt) {
            const size_t go = ((size_t)e * TT + m0b + row) * II + n0b + seg * 8;
            *(uint4*)(g_acthi + go) = *(const uint4*)(stHi + (row * 72 + seg * 8) * 2);
            *(uint4*)(g_actlo + go) = *(const uint4*)(stLo + (row * 72 + seg * 8) * 2);
        }
    }
}

// ---------------- gemm2: warp-MMA, split bf16, 3-term ----------------
#define G2_AB  (128 * STRIDE_H * 2)
#define G2_BB  (64 * STRIDE_H * 2)
#define G2_BUF (2 * G2_AB + 2 * G2_BB)     // 30720
#define G2_SMEM (2 * G2_BUF + 64)

__global__ __launch_bounds__(256)
void gemm2_wm() {
    extern __shared__ char smem[];
    const int e    = blockIdx.z;
    const int cnt  = g_counts[e];
    const int m0b  = blockIdx.y * 128;
    if (m0b >= cnt) return;
    const int n0b  = blockIdx.x * 64;
    const int mrows = (cnt - m0b < 128) ? (cnt - m0b) : 128;

    const int tid  = threadIdx.x;
    const int wid  = tid >> 5, lane = tid & 31;
    const int m0w  = (wid & 3) * 32;
    const int n0w  = (wid >> 2) * 32;
    const uint32_t sb = smem_to_u32(smem);

    const __nv_bfloat16* Ahi = g_acthi + ((size_t)e * TT + m0b) * II;
    const __nv_bfloat16* Alo = g_actlo + ((size_t)e * TT + m0b) * II;
    const __nv_bfloat16* Bhi = g_w2hi + ((size_t)e * HH + n0b) * II;
    const __nv_bfloat16* Blo = g_w2lo + ((size_t)e * HH + n0b) * II;

    float acc[2][4][4];
    #pragma unroll
    for (int mt = 0; mt < 2; mt++)
        #pragma unroll
        for (int nt = 0; nt < 4; nt++)
            #pragma unroll
            for (int j = 0; j < 4; j++) acc[mt][nt][j] = 0.f;

    auto load_chunk = [&](int buf, int c) {
        const int k0 = c * 32;
        const uint32_t base = sb + buf * G2_BUF;
        #pragma unroll
        for (int pl = 0; pl < 2; pl++) {
            const __nv_bfloat16* sp = pl ? Alo : Ahi;
            #pragma unroll
            for (int it = 0; it < 2; it++) {
                const int idx = tid + it * 256;
                const int row = idx >> 2, seg = idx & 3;
                const uint32_t dst = base + pl * G2_AB + row * 80 + seg * 16;
                const uint32_t ssz = (row < mrows) ? 16u : 0u;
                CP_ASYNC16Z(dst, sp + (size_t)row * II + k0 + seg * 8, ssz);
            }
        }
        #pragma unroll
        for (int pl = 0; pl < 2; pl++) {
            const __nv_bfloat16* sp = pl ? Blo : Bhi;
            const int row = tid >> 2, seg = tid & 3;
            const uint32_t dst = base + 2 * G2_AB + pl * G2_BB + row * 80 + seg * 16;
            CP_ASYNC16(dst, sp + (size_t)row * II + k0 + seg * 8);
        }
        CP_COMMIT();
    };

    const int NC = II / 32;   // 32
    load_chunk(0, 0);
    load_chunk(1, 1);

    for (int c = 0; c < NC; c++) {
        if (c == NC - 1) { CP_WAIT(0); } else { CP_WAIT(1); }
        __syncthreads();
        const int buf = c & 1;
        const uint32_t aH = sb + buf * G2_BUF;
        const uint32_t aL = aH + G2_AB;
        const uint32_t bH = aH + 2 * G2_AB;
        const uint32_t bL = bH + G2_BB;
        #pragma unroll
        for (int kk = 0; kk < 2; kk++) {
            const uint32_t koff = (kk * 16 + 2 * (lane & 3)) * 2;
            uint32_t ah[2][4], al[2][4];
            #pragma unroll
            for (int mt = 0; mt < 2; mt++) {
                const uint32_t ro = (m0w + mt * 16 + (lane >> 2)) * 80 + koff;
                ah[mt][0] = lds32(aH + ro);       ah[mt][1] = lds32(aH + ro + 640);
                ah[mt][2] = lds32(aH + ro + 16);  ah[mt][3] = lds32(aH + ro + 656);
                al[mt][0] = lds32(aL + ro);       al[mt][1] = lds32(aL + ro + 640);
                al[mt][2] = lds32(aL + ro + 16);  al[mt][3] = lds32(aL + ro + 656);
            }
            uint32_t bh[4][2], bl[4][2];
            #pragma unroll
            for (int nt = 0; nt < 4; nt++) {
                const uint32_t ro = (n0w + nt * 8 + (lane >> 2)) * 80 + koff;
                bh[nt][0] = lds32(bH + ro);  bh[nt][1] = lds32(bH + ro + 16);
                bl[nt][0] = lds32(bL + ro);  bl[nt][1] = lds32(bL + ro + 16);
            }
            #pragma unroll
            for (int mt = 0; mt < 2; mt++)
                #pragma unroll
                for (int nt = 0; nt < 4; nt++) {
                    mma16816(acc[mt][nt], ah[mt], bh[nt]);
                    mma16816(acc[mt][nt], al[mt], bh[nt]);
                    mma16816(acc[mt][nt], ah[mt], bl[nt]);
                }
        }
        __syncthreads();
        if (c + 2 < NC) load_chunk(buf, c + 2);
    }

    CP_WAIT(0);
    __syncthreads();
    float* st = (float*)smem;              // 128 x 68 floats
    #pragma unroll
    for (int mt = 0; mt < 2; mt++)
        #pragma unroll
        for (int nt = 0; nt < 4; nt++) {
            const int gr = m0w + mt * 16 + (lane >> 2);
            const int cb = n0w + nt * 8 + 2 * (lane & 3);
            *(float2*)(st + gr * 68 + cb)       = make_float2(acc[mt][nt][0], acc[mt][nt][1]);
            *(float2*)(st + (gr + 8) * 68 + cb) = make_float2(acc[mt][nt][2], acc[mt][nt][3]);
        }
    __syncthreads();
    #pragma unroll
    for (int it = 0; it < 8; it++) {
        const int idx = tid + it * 256;           // 0..2047
        const int row = idx >> 4, seg = idx & 15;
        if (row < mrows)
            *(uint4*)(g_h2 + ((size_t)e * TT + m0b + row) * HH + n0b + seg * 4) =
                *(const uint4*)(st + row * 68 + seg * 4);
    }
}

// ---------------- combine ----------------
__global__ void combine_kernel(float* __restrict__ out) {
    const int t = blockIdx.y;
    const int h = blockIdx.x * blockDim.x + threadIdx.x;
    float s = 0.f;
    #pragma unroll
    for (int k = 0; k < TOPK; k++) {
        const int   fs = g_tslot[t * TOPK + k];
        const float w  = g_twt [t * TOPK + k];
        s += w * g_h2[(size_t)fs * HH + h];
    }
    out[(size_t)t * HH + h] = s;
}

// ---------------- launch ----------------
extern "C" void kernel_launch(void* const* d_in, const int* in_sizes, int n_in,
                              void* d_out, int out_size) {
    const float* hs = (const float*)d_in[0];
    const float* gw = (const float*)d_in[1];
    const float* w1 = (const float*)d_in[2];
    const float* w3 = (const float*)d_in[3];
    const float* w2 = (const float*)d_in[4];
    float* out = (float*)d_out;

    cudaFuncSetAttribute(gemm13_wm, cudaFuncAttributeMaxDynamicSharedMemorySize, G13_SMEM);
    cudaFuncSetAttribute(gemm2_wm,  cudaFuncAttributeMaxDynamicSharedMemorySize, G2_SMEM);

    zero_counts_kernel<<<1, 32>>>();
    router_kernel<<<TT, 256>>>(hs, gw);
    prep_hs_kernel<<<(TT * HH) / 1024, 256>>>(hs);
    prep_w13_kernel<<<dim3(II / 32, HH / 32, EE * 2), dim3(32, 8)>>>(w1, w3);
    prep_w2_kernel <<<dim3(II / 32, HH / 32, EE),     dim3(32, 8)>>>(w2);
    gemm13_wm<<<dim3(II / 64, TT / 128, EE), 256, G13_SMEM>>>(g_hshi);
    gemm2_wm <<<dim3(HH / 64, TT / 128, EE), 256, G2_SMEM>>>();
    combine_kernel<<<dim3(HH / 256, TT), 256>>>(out);
}

// round 4
// speedup vs baseline: 2.3156x; 1.0700x over previous
#include <cuda_runtime.h>
#include <cuda_bf16.h>
#include <cstdint>

#define TT   2048
#define HH   2048
#define II   1024
#define EE   16
#define TOPK 4

// ---------------- PTX helpers (sm_80-level only; target is plain sm_103) -------
__device__ __forceinline__ uint32_t smem_to_u32(const void* p) {
    uint32_t a;
    asm("{ .reg .u64 t; cvta.to.shared.u64 t, %1; cvt.u32.u64 %0, t; }"
        : "=r"(a) : "l"(p));
    return a;
}
#define CP_ASYNC16(dst, src) \
    asm volatile("cp.async.cg.shared.global [%0], [%1], 16;" :: "r"(dst), "l"(src) : "memory")
#define CP_ASYNC16Z(dst, src, ssz) \
    asm volatile("cp.async.cg.shared.global [%0], [%1], 16, %2;" :: "r"(dst), "l"(src), "r"(ssz) : "memory")
#define CP_COMMIT()  asm volatile("cp.async.commit_group;" ::: "memory")
#define CP_WAIT(n)   asm volatile("cp.async.wait_group %0;" :: "n"(n) : "memory")

#define LDSM_X4(r0, r1, r2, r3, addr) \
    asm volatile("ldmatrix.sync.aligned.m8n8.x4.shared.b16 {%0,%1,%2,%3}, [%4];" \
                 : "=r"(r0), "=r"(r1), "=r"(r2), "=r"(r3) : "r"(addr))

// D += A*B  (m16n8k16, bf16 in, f32 accum)
__device__ __forceinline__ void mma16816(float* c, const uint32_t* a, const uint32_t* b) {
    asm volatile(
        "mma.sync.aligned.m16n8k16.row.col.f32.bf16.bf16.f32 "
        "{%0,%1,%2,%3}, {%4,%5,%6,%7}, {%8,%9}, {%0,%1,%2,%3};"
        : "+f"(c[0]), "+f"(c[1]), "+f"(c[2]), "+f"(c[3])
        : "r"(a[0]), "r"(a[1]), "r"(a[2]), "r"(a[3]), "r"(b[0]), "r"(b[1]));
}

// ---------------- scratch ----------------
__device__ int   g_counts[EE];
__device__ int   g_tok[EE * TT];
__device__ int   g_tslot[TT * TOPK];
__device__ float g_twt[TT * TOPK];
__device__ float g_h2[(size_t)EE * TT * HH];
__device__ __nv_bfloat16 g_hshi[(size_t)TT * HH];
__device__ __nv_bfloat16 g_hslo[(size_t)TT * HH];
__device__ __nv_bfloat16 g_acthi[(size_t)EE * TT * II];
__device__ __nv_bfloat16 g_actlo[(size_t)EE * TT * II];
__device__ __nv_bfloat16 g_w13hi[(size_t)EE * 2 * II * HH];  // [e*2+mat][i][h]
__device__ __nv_bfloat16 g_w13lo[(size_t)EE * 2 * II * HH];
__device__ __nv_bfloat16 g_w2hi [(size_t)EE * HH * II];      // [e][h][i]
__device__ __nv_bfloat16 g_w2lo [(size_t)EE * HH * II];

__device__ __forceinline__ void split_bf16(float x, __nv_bfloat16& hi, __nv_bfloat16& lo) {
    hi = __float2bfloat16(x);
    lo = __float2bfloat16(x - __bfloat162float(hi));
}
__device__ __forceinline__ uint32_t pack2(__nv_bfloat16 a, __nv_bfloat16 b) {
    return (uint32_t)__bfloat16_as_ushort(a) | ((uint32_t)__bfloat16_as_ushort(b) << 16);
}

// ---------------- router ----------------
__global__ void zero_counts_kernel() {
    if (threadIdx.x < EE) g_counts[threadIdx.x] = 0;
}

__global__ void router_kernel(const float* __restrict__ hs,
                              const float* __restrict__ gw) {
    const int t = blockIdx.x;
    __shared__ float xs[HH];
    __shared__ float logits[EE];
    const float* x = hs + (size_t)t * HH;
    for (int i = threadIdx.x; i < HH; i += blockDim.x) xs[i] = x[i];
    __syncthreads();
    const int warp = threadIdx.x >> 5, lane = threadIdx.x & 31;
    for (int e = warp; e < EE; e += 8) {
        const float* g = gw + (size_t)e * HH;
        float s = 0.f;
        for (int k = lane; k < HH; k += 32) s += xs[k] * g[k];
        #pragma unroll
        for (int o = 16; o; o >>= 1) s += __shfl_xor_sync(0xffffffffu, s, o);
        if (lane == 0) logits[e] = s;
    }
    __syncthreads();
    if (threadIdx.x == 0) {
        float lv[EE];
        #pragma unroll
        for (int e = 0; e < EE; e++) lv[e] = logits[e];
        int idx[TOPK]; float val[TOPK];
        #pragma unroll
        for (int k = 0; k < TOPK; k++) {
            float best = -1e30f; int bi = 0;
            for (int e = 0; e < EE; e++) if (lv[e] > best) { best = lv[e]; bi = e; }
            idx[k] = bi; val[k] = best; lv[bi] = -1e30f;
        }
        const float m = val[0];
        float w[TOPK], se = 0.f;
        #pragma unroll
        for (int k = 0; k < TOPK; k++) { w[k] = __expf(val[k] - m); se += w[k]; }
        const float inv = 1.f / se;
        #pragma unroll
        for (int k = 0; k < TOPK; k++) {
            const int e = idx[k];
            const int slot = atomicAdd(&g_counts[e], 1);
            g_tok[e * TT + slot]  = t;
            g_tslot[t * TOPK + k] = e * TT + slot;
            g_twt[t * TOPK + k]   = w[k] * inv;
        }
    }
}

// ---------------- prepass: split hs ----------------
__global__ void prep_hs_kernel(const float* __restrict__ hs) {
    const size_t i = ((size_t)blockIdx.x * 256 + threadIdx.x) * 4;
    const float4 v = *(const float4*)(hs + i);
    __nv_bfloat16 h0, l0, h1, l1, h2, l2, h3, l3;
    split_bf16(v.x, h0, l0); split_bf16(v.y, h1, l1);
    split_bf16(v.z, h2, l2); split_bf16(v.w, h3, l3);
    *(uint2*)(g_hshi + i) = make_uint2(pack2(h0, h1), pack2(h2, h3));
    *(uint2*)(g_hslo + i) = make_uint2(pack2(l0, l1), pack2(l2, l3));
}

// ---------------- prepass: transpose + split weights ----------------
__global__ void prep_w13_kernel(const float* __restrict__ w1,
                                const float* __restrict__ w3) {
    __shared__ float s[32][33];
    const int z = blockIdx.z;            // e*2+mat
    const int e = z >> 1, mat = z & 1;
    const float* src = (mat ? w3 : w1) + (size_t)e * HH * II;
    const int i0 = blockIdx.x * 32, h0 = blockIdx.y * 32;
    const int tx = threadIdx.x, ty = threadIdx.y;
    #pragma unroll
    for (int j = 0; j < 4; j++)
        s[ty + 8 * j][tx] = src[(size_t)(h0 + ty + 8 * j) * II + i0 + tx];
    __syncthreads();
    #pragma unroll
    for (int j = 0; j < 4; j++) {
        const float x = s[tx][ty + 8 * j];
        __nv_bfloat16 hi, lo; split_bf16(x, hi, lo);
        const size_t o = ((size_t)z * II + i0 + ty + 8 * j) * HH + h0 + tx;
        g_w13hi[o] = hi; g_w13lo[o] = lo;
    }
}

__global__ void prep_w2_kernel(const float* __restrict__ w2) {
    __shared__ float s[32][33];
    const int e = blockIdx.z;
    const float* src = w2 + (size_t)e * II * HH;
    const int i0 = blockIdx.x * 32, h0 = blockIdx.y * 32;
    const int tx = threadIdx.x, ty = threadIdx.y;
    #pragma unroll
    for (int j = 0; j < 4; j++)
        s[ty + 8 * j][tx] = src[(size_t)(i0 + ty + 8 * j) * HH + h0 + tx];
    __syncthreads();
    #pragma unroll
    for (int j = 0; j < 4; j++) {
        const float x = s[tx][ty + 8 * j];
        __nv_bfloat16 hi, lo; split_bf16(x, hi, lo);
        const size_t o = ((size_t)e * HH + h0 + ty + 8 * j) * II + i0 + tx;
        g_w2hi[o] = hi; g_w2lo[o] = lo;
    }
}

// ---------------- gemm13: warp-MMA, split bf16, 3-term, ldmatrix ----------------
// tile: 128 (m) x 64 (n) for BOTH h1 and h3; BK=32, double-buffered cp.async
#define STRIDE_H 40                        // halves per smem row (80B)
#define G13_AB   (128 * STRIDE_H * 2)      // 10240 per A plane
#define G13_BB   (64 * STRIDE_H * 2)       // 5120 per B plane
#define G13_BUF  (2 * G13_AB + 4 * G13_BB) // 40960 per buffer
#define G13_SMEM (2 * G13_BUF + 1024)

__global__ __launch_bounds__(256)
void gemm13_wm() {
    extern __shared__ char smem[];
    const int e    = blockIdx.z;
    const int cnt  = g_counts[e];
    const int m0b  = blockIdx.y * 128;
    if (m0b >= cnt) return;
    const int n0b  = blockIdx.x * 64;

    const int tid  = threadIdx.x;
    const int wid  = tid >> 5, lane = tid & 31;
    const int m0w  = (wid & 3) * 32;
    const int n0w  = (wid >> 2) * 32;
    const uint32_t sb = smem_to_u32(smem);

    int* rowTokS = (int*)(smem + 2 * G13_BUF);
    if (tid < 128) rowTokS[tid] = (m0b + tid < cnt) ? g_tok[e * TT + m0b + tid] : -1;
    __syncthreads();

    const __nv_bfloat16* srcB[4] = {
        g_w13hi + ((size_t)(e * 2 + 0) * II + n0b) * HH,
        g_w13lo + ((size_t)(e * 2 + 0) * II + n0b) * HH,
        g_w13hi + ((size_t)(e * 2 + 1) * II + n0b) * HH,
        g_w13lo + ((size_t)(e * 2 + 1) * II + n0b) * HH };

    float acc1[2][4][4], acc3[2][4][4];
    #pragma unroll
    for (int mt = 0; mt < 2; mt++)
        #pragma unroll
        for (int nt = 0; nt < 4; nt++)
            #pragma unroll
            for (int j = 0; j < 4; j++) { acc1[mt][nt][j] = 0.f; acc3[mt][nt][j] = 0.f; }

    // ldmatrix per-lane row offsets
    const uint32_t aRowOff = (uint32_t)((lane & 15) * 80 + ((lane >> 4) & 1) * 16);
    const uint32_t bRowOff = (uint32_t)((((lane >> 4) & 1) * 8 + (lane & 7)) * 80 +
                                        ((lane >> 3) & 1) * 16);

    auto load_chunk = [&](int buf, int c) {
        const int k0 = c * 32;
        const uint32_t base = sb + buf * G13_BUF;
        #pragma unroll
        for (int pl = 0; pl < 2; pl++) {
            const __nv_bfloat16* sp = pl ? g_hslo : g_hshi;
            #pragma unroll
            for (int it = 0; it < 2; it++) {
                const int idx = tid + it * 256;
                const int row = idx >> 2, seg = idx & 3;
                const int tok = rowTokS[row];
                const uint32_t dst = base + pl * G13_AB + row * 80 + seg * 16;
                const __nv_bfloat16* s =
                    (tok >= 0 ? sp + (size_t)tok * HH : sp) + k0 + seg * 8;
                const uint32_t ssz = (tok >= 0) ? 16u : 0u;
                CP_ASYNC16Z(dst, s, ssz);
            }
        }
        #pragma unroll
        for (int pl = 0; pl < 4; pl++) {
            const int row = tid >> 2, seg = tid & 3;
            const uint32_t dst = base + 2 * G13_AB + pl * G13_BB + row * 80 + seg * 16;
            CP_ASYNC16(dst, srcB[pl] + (size_t)row * HH + k0 + seg * 8);
        }
        CP_COMMIT();
    };

    const int NC = HH / 32;   // 64
    load_chunk(0, 0);
    load_chunk(1, 1);

    for (int c = 0; c < NC; c++) {
        if (c == NC - 1) { CP_WAIT(0); } else { CP_WAIT(1); }
        __syncthreads();
        const int buf = c & 1;
        const uint32_t aH = sb + buf * G13_BUF;
        const uint32_t aL = aH + G13_AB;
        const uint32_t bB = aH + 2 * G13_AB;
        #pragma unroll
        for (int kk = 0; kk < 2; kk++) {
            uint32_t ah[2][4], al[2][4];
            #pragma unroll
            for (int mt = 0; mt < 2; mt++) {
                const uint32_t ao = (uint32_t)((m0w + mt * 16) * 80 + kk * 32) + aRowOff;
                LDSM_X4(ah[mt][0], ah[mt][1], ah[mt][2], ah[mt][3], aH + ao);
                LDSM_X4(al[mt][0], al[mt][1], al[mt][2], al[mt][3], aL + ao);
            }
            #pragma unroll
            for (int np = 0; np < 2; np++) {
                const uint32_t bo = (uint32_t)((n0w + np * 16) * 80 + kk * 32) + bRowOff;
                uint32_t b1h[4], b1l[4], b3h[4], b3l[4];
                LDSM_X4(b1h[0], b1h[1], b1h[2], b1h[3], bB + bo);
                LDSM_X4(b1l[0], b1l[1], b1l[2], b1l[3], bB + G13_BB + bo);
                LDSM_X4(b3h[0], b3h[1], b3h[2], b3h[3], bB + 2 * G13_BB + bo);
                LDSM_X4(b3l[0], b3l[1], b3l[2], b3l[3], bB + 3 * G13_BB + bo);
                #pragma unroll
                for (int mt = 0; mt < 2; mt++)
                    #pragma unroll
                    for (int s = 0; s < 2; s++) {
                        const int nt = np * 2 + s;
                        mma16816(acc1[mt][nt], ah[mt], b1h + 2 * s);
                        mma16816(acc1[mt][nt], al[mt], b1h + 2 * s);
                        mma16816(acc1[mt][nt], ah[mt], b1l + 2 * s);
                        mma16816(acc3[mt][nt], ah[mt], b3h + 2 * s);
                        mma16816(acc3[mt][nt], al[mt], b3h + 2 * s);
                        mma16816(acc3[mt][nt], ah[mt], b3l + 2 * s);
                    }
            }
        }
        __syncthreads();
        if (c + 2 < NC) load_chunk(buf, c + 2);
    }

    // epilogue: silu(h1)*h3 -> split bf16 -> smem stage -> coalesced store
    CP_WAIT(0);
    __syncthreads();
    char* stHi = smem;                     // 128 x 72 halves
    char* stLo = smem + 128 * 72 * 2;
    #pragma unroll
    for (int mt = 0; mt < 2; mt++)
        #pragma unroll
        for (int nt = 0; nt < 4; nt++) {
            const int gr = m0w + mt * 16 + (lane >> 2);
            const int cb = n0w + nt * 8 + 2 * (lane & 3);
            float a[4];
            #pragma unroll
            for (int j = 0; j < 4; j++) {
                const float x = acc1[mt][nt][j];
                a[j] = (x / (1.f + __expf(-x))) * acc3[mt][nt][j];
            }
            __nv_bfloat16 h0, l0, h1, l1, h2, l2, h3, l3;
            split_bf16(a[0], h0, l0); split_bf16(a[1], h1, l1);
            split_bf16(a[2], h2, l2); split_bf16(a[3], h3, l3);
            *(uint32_t*)(stHi + (gr * 72 + cb) * 2)       = pack2(h0, h1);
            *(uint32_t*)(stHi + ((gr + 8) * 72 + cb) * 2) = pack2(h2, h3);
            *(uint32_t*)(stLo + (gr * 72 + cb) * 2)       = pack2(l0, l1);
            *(uint32_t*)(stLo + ((gr + 8) * 72 + cb) * 2) = pack2(l2, l3);
        }
    __syncthreads();
    #pragma unroll
    for (int it = 0; it < 4; it++) {
        const int idx = tid + it * 256;           // 0..1023
        const int row = idx >> 3, seg = idx & 7;
        if (m0b + row < cnt) {
            const size_t go = ((size_t)e * TT + m0b + row) * II + n0b + seg * 8;
            *(uint4*)(g_acthi + go) = *(const uint4*)(stHi + (row * 72 + seg * 8) * 2);
            *(uint4*)(g_actlo + go) = *(const uint4*)(stLo + (row * 72 + seg * 8) * 2);
        }
    }
}

// ---------------- gemm2: warp-MMA, split bf16, 3-term, ldmatrix ----------------
#define G2_AB  (128 * STRIDE_H * 2)
#define G2_BB  (64 * STRIDE_H * 2)
#define G2_BUF (2 * G2_AB + 2 * G2_BB)     // 30720
#define G2_SMEM (2 * G2_BUF + 64)

__global__ __launch_bounds__(256)
void gemm2_wm() {
    extern __shared__ char smem[];
    const int e    = blockIdx.z;
    const int cnt  = g_counts[e];
    const int m0b  = blockIdx.y * 128;
    if (m0b >= cnt) return;
    const int n0b  = blockIdx.x * 64;
    const int mrows = (cnt - m0b < 128) ? (cnt - m0b) : 128;

    const int tid  = threadIdx.x;
    const int wid  = tid >> 5, lane = tid & 31;
    const int m0w  = (wid & 3) * 32;
    const int n0w  = (wid >> 2) * 32;
    const uint32_t sb = smem_to_u32(smem);

    const __nv_bfloat16* Ahi = g_acthi + ((size_t)e * TT + m0b) * II;
    const __nv_bfloat16* Alo = g_actlo + ((size_t)e * TT + m0b) * II;
    const __nv_bfloat16* Bhi = g_w2hi + ((size_t)e * HH + n0b) * II;
    const __nv_bfloat16* Blo = g_w2lo + ((size_t)e * HH + n0b) * II;

    float acc[2][4][4];
    #pragma unroll
    for (int mt = 0; mt < 2; mt++)
        #pragma unroll
        for (int nt = 0; nt < 4; nt++)
            #pragma unroll
            for (int j = 0; j < 4; j++) acc[mt][nt][j] = 0.f;

    const uint32_t aRowOff = (uint32_t)((lane & 15) * 80 + ((lane >> 4) & 1) * 16);
    const uint32_t bRowOff = (uint32_t)((((lane >> 4) & 1) * 8 + (lane & 7)) * 80 +
                                        ((lane >> 3) & 1) * 16);

    auto load_chunk = [&](int buf, int c) {
        const int k0 = c * 32;
        const uint32_t base = sb + buf * G2_BUF;
        #pragma unroll
        for (int pl = 0; pl < 2; pl++) {
            const __nv_bfloat16* sp = pl ? Alo : Ahi;
            #pragma unroll
            for (int it = 0; it < 2; it++) {
                const int idx = tid + it * 256;
                const int row = idx >> 2, seg = idx & 3;
                const uint32_t dst = base + pl * G2_AB + row * 80 + seg * 16;
                const uint32_t ssz = (row < mrows) ? 16u : 0u;
                CP_ASYNC16Z(dst, sp + (size_t)row * II + k0 + seg * 8, ssz);
            }
        }
        #pragma unroll
        for (int pl = 0; pl < 2; pl++) {
            const __nv_bfloat16* sp = pl ? Blo : Bhi;
            const int row = tid >> 2, seg = tid & 3;
            const uint32_t dst = base + 2 * G2_AB + pl * G2_BB + row * 80 + seg * 16;
            CP_ASYNC16(dst, sp + (size_t)row * II + k0 + seg * 8);
        }
        CP_COMMIT();
    };

    const int NC = II / 32;   // 32
    load_chunk(0, 0);
    load_chunk(1, 1);

    for (int c = 0; c < NC; c++) {
        if (c == NC - 1) { CP_WAIT(0); } else { CP_WAIT(1); }
        __syncthreads();
        const int buf = c & 1;
        const uint32_t aH = sb + buf * G2_BUF;
        const uint32_t aL = aH + G2_AB;
        const uint32_t bH = aH + 2 * G2_AB;
        const uint32_t bL = bH + G2_BB;
        #pragma unroll
        for (int kk = 0; kk < 2; kk++) {
            uint32_t ah[2][4], al[2][4];
            #pragma unroll
            for (int mt = 0; mt < 2; mt++) {
                const uint32_t ao = (uint32_t)((m0w + mt * 16) * 80 + kk * 32) + aRowOff;
                LDSM_X4(ah[mt][0], ah[mt][1], ah[mt][2], ah[mt][3], aH + ao);
                LDSM_X4(al[mt][0], al[mt][1], al[mt][2], al[mt][3], aL + ao);
            }
            #pragma unroll
            for (int np = 0; np < 2; np++) {
                const uint32_t bo = (uint32_t)((n0w + np * 16) * 80 + kk * 32) + bRowOff;
                uint32_t bh[4], bl[4];
                LDSM_X4(bh[0], bh[1], bh[2], bh[3], bH + bo);
                LDSM_X4(bl[0], bl[1], bl[2], bl[3], bL + bo);
                #pragma unroll
                for (int mt = 0; mt < 2; mt++)
                    #pragma unroll
                    for (int s = 0; s < 2; s++) {
                        const int nt = np * 2 + s;
                        mma16816(acc[mt][nt], ah[mt], bh + 2 * s);
                        mma16816(acc[mt][nt], al[mt], bh + 2 * s);
                        mma16816(acc[mt][nt], ah[mt], bl + 2 * s);
                    }
            }
        }
        __syncthreads();
        if (c + 2 < NC) load_chunk(buf, c + 2);
    }

    CP_WAIT(0);
    __syncthreads();
    float* st = (float*)smem;              // 128 x 68 floats
    #pragma unroll
    for (int mt = 0; mt < 2; mt++)
        #pragma unroll
        for (int nt = 0; nt < 4; nt++) {
            const int gr = m0w + mt * 16 + (lane >> 2);
            const int cb = n0w + nt * 8 + 2 * (lane & 3);
            *(float2*)(st + gr * 68 + cb)       = make_float2(acc[mt][nt][0], acc[mt][nt][1]);
            *(float2*)(st + (gr + 8) * 68 + cb) = make_float2(acc[mt][nt][2], acc[mt][nt][3]);
        }
    __syncthreads();
    #pragma unroll
    for (int it = 0; it < 8; it++) {
        const int idx = tid + it * 256;           // 0..2047
        const int row = idx >> 4, seg = idx & 15;
        if (row < mrows)
            *(uint4*)(g_h2 + ((size_t)e * TT + m0b + row) * HH + n0b + seg * 4) =
                *(const uint4*)(st + row * 68 + seg * 4);
    }
}

// ---------------- combine ----------------
__global__ void combine_kernel(float* __restrict__ out) {
    const int t = blockIdx.y;
    const int h = blockIdx.x * blockDim.x + threadIdx.x;
    float s = 0.f;
    #pragma unroll
    for (int k = 0; k < TOPK; k++) {
        const int   fs = g_tslot[t * TOPK + k];
        const float w  = g_twt [t * TOPK + k];
        s += w * g_h2[(size_t)fs * HH + h];
    }
    out[(size_t)t * HH + h] = s;
}

// ---------------- launch ----------------
extern "C" void kernel_launch(void* const* d_in, const int* in_sizes, int n_in,
                              void* d_out, int out_size) {
    const float* hs = (const float*)d_in[0];
    const float* gw = (const float*)d_in[1];
    const float* w1 = (const float*)d_in[2];
    const float* w3 = (const float*)d_in[3];
    const float* w2 = (const float*)d_in[4];
    float* out = (float*)d_out;

    cudaFuncSetAttribute(gemm13_wm, cudaFuncAttributeMaxDynamicSharedMemorySize, G13_SMEM);
    cudaFuncSetAttribute(gemm2_wm,  cudaFuncAttributeMaxDynamicSharedMemorySize, G2_SMEM);

    zero_counts_kernel<<<1, 32>>>();
    router_kernel<<<TT, 256>>>(hs, gw);
    prep_hs_kernel<<<(TT * HH) / 1024, 256>>>(hs);
    prep_w13_kernel<<<dim3(II / 32, HH / 32, EE * 2), dim3(32, 8)>>>(w1, w3);
    prep_w2_kernel <<<dim3(II / 32, HH / 32, EE),     dim3(32, 8)>>>(w2);
    gemm13_wm<<<dim3(II / 64, TT / 128, EE), 256, G13_SMEM>>>();
    gemm2_wm <<<dim3(HH / 64, TT / 128, EE), 256, G2_SMEM>>>();
    combine_kernel<<<dim3(HH / 256, TT), 256>>>(out);
}